// round 13
// baseline (speedup 1.0000x reference)
#include <cuda_runtime.h>
#include <cuda_bf16.h>
#include <math.h>
#include <stdint.h>

// ---------------------------------------------------------------- constants
#define B_    2
#define N_    16384
#define S_    4096
#define D1_   128
#define D2_   256
#define CIN_  397
#define C_    128
#define NCLS  13

#define OUT0_OFF 0
#define OUT1_OFF (B_ * C_ * N_)
#define OUT2_OFF (OUT1_OFF + B_ * N_ * C_)

// ---------------------------------------------------------------- scratch
__device__ uint32_t g_Wfrag[6][16384];   // lane-ordered MMA B fragments
__device__ float g_bfuse[C_];
__device__ float g_be1[C_];
__device__ float g_be2[C_];
__device__ float g_bp1[C_];
__device__ float g_Wp2[NCLS * C_];
__device__ float g_bp2[NCLS];
__device__ float g_W3f[C_ * NCLS];
__device__ float4 g_xyz2p[B_ * S_];      // packed candidates (x, y, z, -0.5*|c|^2)
__device__ float g_ZY[B_ * S_ * C_];
__device__ int   g_idx[B_ * N_ * 3];
__device__ float g_w[B_ * N_ * 3];
__device__ float g_p1T[B_ * N_ * D1_];
__device__ float g_p2T[B_ * S_ * D2_];

// ---------------------------------------------------------------- helpers
__device__ __forceinline__ uint32_t smem_u32(const void* p) {
    uint32_t a;
    asm("{ .reg .u64 t; cvta.to.shared.u64 t, %1; cvt.u32.u64 %0, t; }"
        : "=r"(a) : "l"(p));
    return a;
}

#define CVT2(res, a, b) \
    asm("cvt.rn.satfinite.bf16x2.f32 %0, %1, %2;" : "=r"(res) : "f"(b), "f"(a))

#define LDSM_X4(r0, r1, r2, r3, addr) \
    asm volatile("ldmatrix.sync.aligned.m8n8.x4.shared.b16 {%0,%1,%2,%3}, [%4];" \
                 : "=r"(r0), "=r"(r1), "=r"(r2), "=r"(r3) : "r"(addr))

#define STSM_X4(addr, r0, r1, r2, r3) \
    asm volatile("stmatrix.sync.aligned.m8n8.x4.shared.b16 [%0], {%1,%2,%3,%4};" \
                 :: "r"(addr), "r"(r0), "r"(r1), "r"(r2), "r"(r3))

#define MMA16816(c0, c1, c2, c3, a0, a1, a2, a3, b0, b1) \
    asm volatile("mma.sync.aligned.m16n8k16.row.col.f32.bf16.bf16.f32 " \
                 "{%0,%1,%2,%3}, {%4,%5,%6,%7}, {%8,%9}, {%0,%1,%2,%3};" \
                 : "+f"(c0), "+f"(c1), "+f"(c2), "+f"(c3) \
                 : "r"(a0), "r"(a1), "r"(a2), "r"(a3), "r"(b0), "r"(b1))

// ---------------------------------------------------------------- smem layout (bytes) for GEMM kernels
#define SM_BIAS 0
#define SM_BP2  2048
#define SM_WP2  2112
#define SM_AOP  9216                     // 32768: A tile 64 rows x 512B
#define SM_D    (9216 + 32768)           // fp32 D 64 x 132 = 33792
#define SM_TOT  (41984 + 33792)          // 75776
#define DPITCH  132

#define PREP_BLOCKS 112

// ---------------------------------------------------------------- fold helpers
__device__ __forceinline__ float fold_scale(const float* bn, int Cout, int o) {
    return bn[o] * rsqrtf(bn[3 * Cout + o] + 1e-5f);
}

// keep top-3 LARGEST s; strict > keeps earlier index on ties
__device__ __forceinline__ void insert3max(float s, int si,
                                           float& s0, float& s1, float& s2,
                                           int& i0, int& i1, int& i2) {
    if (s > s2) {
        if (s > s1) {
            s2 = s1; i2 = i1;
            if (s > s0) { s1 = s0; i1 = i0; s0 = s; i0 = si; }
            else        { s1 = s;  i1 = si; }
        } else { s2 = s; i2 = si; }
    }
}

// branchless top-3 VALUES sorting network (s0 >= s1 >= s2)
__device__ __forceinline__ void net3(float t, float& s0, float& s1, float& s2) {
    float n2 = fmaxf(s2, fminf(s1, t));
    float n1 = fmaxf(s1, fminf(s0, t));
    s0 = fmaxf(s0, t);
    s1 = n1;
    s2 = n2;
}

// ---------------------------------------------------------------- prep: weights + xyz2 packing
__global__ void __launch_bounds__(256) prep_kernel(
    const float* __restrict__ xyz2,
    const float* __restrict__ fW, const float* __restrict__ fb, const float* __restrict__ fbn,
    const float* __restrict__ e1W, const float* __restrict__ e1b, const float* __restrict__ e1bn,
    const float* __restrict__ e2W, const float* __restrict__ e2b, const float* __restrict__ e2bn,
    const float* __restrict__ p1W, const float* __restrict__ p1b, const float* __restrict__ p1bn,
    const float* __restrict__ p2W, const float* __restrict__ p2b, const float* __restrict__ p2bn) {
    const int FRAG_END = 6 * 8 * 16 * 32;   // 24576
    const int BIAS_END = FRAG_END + 512;
    const int BP2_END = BIAS_END + NCLS;
    const int WP2_END = BP2_END + NCLS * 128;
    const int W3F_END = WP2_END + 128 * NCLS;
    const int XYZ_END = W3F_END + B_ * S_;
    for (int i = blockIdx.x * 256 + threadIdx.x; i < XYZ_END;
         i += PREP_BLOCKS * 256) {
        if (i < FRAG_END) {
            int t = i >> 12;
            int rem = i & 4095;
            int ksg = rem >> 9;
            int nblk = (rem >> 5) & 15;
            int lane = rem & 31;
            int n = nblk * 8 + (lane >> 2);
            int k = ksg * 16 + ((lane & 3) << 1);
            const float* src;
            int ld;
            float s;
            if (t == 0)      { src = fW;        ld = CIN_; s = fold_scale(fbn, 128, n); }
            else if (t == 1) { src = fW + 128;  ld = CIN_; s = fold_scale(fbn, 128, n); }
            else if (t == 2) { src = fW + 256;  ld = CIN_; s = fold_scale(fbn, 128, n); }
            else if (t == 3) { src = e1W;       ld = 128;  s = fold_scale(e1bn, 128, n); }
            else if (t == 4) { src = e2W;       ld = 128;  s = fold_scale(e2bn, 128, n); }
            else             { src = p1W;       ld = 128;  s = fold_scale(p1bn, 128, n); }
            const float* rowp = src + (long)n * ld + k;
            float w0 = rowp[0] * s, w1 = rowp[1] * s;
            float w8 = rowp[8] * s, w9 = rowp[9] * s;
            uint32_t h0, h1;
            CVT2(h0, w0, w1);
            CVT2(h1, w8, w9);
            float l0a = w0 - __uint_as_float(h0 << 16);
            float l0b = w1 - __uint_as_float(h0 & 0xffff0000u);
            float l1a = w8 - __uint_as_float(h1 << 16);
            float l1b = w9 - __uint_as_float(h1 & 0xffff0000u);
            uint32_t lo0, lo1;
            CVT2(lo0, l0a, l0b);
            CVT2(lo1, l1a, l1b);
            int off = ksg * 1024 + nblk * 64 + lane * 2;
            g_Wfrag[t][off + 0] = h0;
            g_Wfrag[t][off + 1] = h1;
            g_Wfrag[t][8192 + off + 0] = lo0;
            g_Wfrag[t][8192 + off + 1] = lo1;
        } else if (i < BIAS_END) {
            int j = i - FRAG_END;
            int which = j >> 7, c = j & 127;
            const float *b, *bn;
            float* dst;
            if (which == 0)      { b = fb;  bn = fbn;  dst = g_bfuse; }
            else if (which == 1) { b = e1b; bn = e1bn; dst = g_be1; }
            else if (which == 2) { b = e2b; bn = e2bn; dst = g_be2; }
            else                 { b = p1b; bn = p1bn; dst = g_bp1; }
            float s = fold_scale(bn, 128, c);
            dst[c] = (b[c] - bn[2 * 128 + c]) * s + bn[128 + c];
        } else if (i < BP2_END) {
            int o = i - BIAS_END;
            float s = fold_scale(p2bn, NCLS, o);
            g_bp2[o] = (p2b[o] - p2bn[2 * NCLS + o]) * s + p2bn[NCLS + o];
        } else if (i < WP2_END) {
            int j = i - BP2_END;
            int o = j >> 7;
            float s = fold_scale(p2bn, NCLS, o);
            g_Wp2[j] = p2W[j] * s;
        } else if (i < W3F_END) {
            int j = i - WP2_END;
            int o = j / NCLS;
            float s = fold_scale(fbn, 128, o);
            g_W3f[j] = fW[o * CIN_ + 384 + (j - o * NCLS)] * s;
        } else {
            int j = i - W3F_END;           // 0 .. B*S-1
            const float* p = xyz2 + (long)j * 3;
            float x = p[0], y = p[1], z = p[2];
            g_xyz2p[j] = make_float4(x, y, z, -0.5f * (x * x + y * y + z * z));
        }
    }
}

// ---------------------------------------------------------------- both transposes
__global__ void __launch_bounds__(256) transpose_both(const float* __restrict__ p1,
                                                      const float* __restrict__ p2) {
    __shared__ float t[32][33];
    const int tid = threadIdx.x;
    const int tx = tid & 31;
    const int ty = tid >> 5;
    const float* src;
    float* dst;
    int C, Nn, n0, c0, b;
    if (blockIdx.x < 4096) {
        int local = blockIdx.x;
        b = local >> 11;
        int rem = local & 2047;
        c0 = (rem >> 9) * 32;
        n0 = (rem & 511) * 32;
        C = 128; Nn = N_;
        src = p1; dst = g_p1T;
    } else {
        int local = blockIdx.x - 4096;
        b = local >> 10;
        int rem = local & 1023;
        c0 = (rem >> 7) * 32;
        n0 = (rem & 127) * 32;
        C = 256; Nn = S_;
        src = p2; dst = g_p2T;
    }
    const float* s = src + (long)b * C * Nn;
    float* d = dst + (long)b * Nn * C;
    for (int i = ty; i < 32; i += 8)
        t[i][tx] = s[(long)(c0 + i) * Nn + n0 + tx];
    __syncthreads();
    for (int i = ty; i < 32; i += 8)
        d[(long)(n0 + i) * C + c0 + tx] = t[tx][i];
}

// ---------------------------------------------------------------- top3 v3: branchless 2-pass
// grid = 512; block = 64 queries x 8 segments (512 cands each); 2 queries/thread
__global__ void __launch_bounds__(256) top3_kernel(const float* __restrict__ xyz1) {
    __shared__ float ms[8 * 3 * 64];
    __shared__ int   mx[8 * 3 * 64];
    __shared__ float thr[64];
    const int tid = threadIdx.x;
    const int blk = blockIdx.x;               // 0..511
    const int b = blk >> 8;
    const int q0 = (blk & 255) * 64;
    const int qg = tid & 31;                  // 32 groups x 2 queries
    const int seg = tid >> 5;                 // 0..7

    float qx[2], qy[2], qz[2];
#pragma unroll
    for (int u = 0; u < 2; ++u) {
        const float* q = xyz1 + ((long)b * N_ + q0 + qg * 2 + u) * 3;
        qx[u] = q[0]; qy[u] = q[1]; qz[u] = q[2];
    }

    const float4* cand = g_xyz2p + (long)b * S_ + seg * 512;
    const int sbase = seg * 512;

    // -------- pass 1: branchless top-3 VALUES
    float a0[2], a1[2], a2[2];
#pragma unroll
    for (int u = 0; u < 2; ++u) { a0[u] = -3.4e38f; a1[u] = -3.4e38f; a2[u] = -3.4e38f; }

    for (int j = 0; j < 512; j += 4) {
        float4 ca = cand[j], cb = cand[j + 1], cc = cand[j + 2], cd = cand[j + 3];
#pragma unroll
        for (int u = 0; u < 2; ++u) {
            float sa = fmaf(qx[u], ca.x, fmaf(qy[u], ca.y, fmaf(qz[u], ca.z, ca.w)));
            float sb = fmaf(qx[u], cb.x, fmaf(qy[u], cb.y, fmaf(qz[u], cb.z, cb.w)));
            float sc = fmaf(qx[u], cc.x, fmaf(qy[u], cc.y, fmaf(qz[u], cc.z, cc.w)));
            float sd = fmaf(qx[u], cd.x, fmaf(qy[u], cd.y, fmaf(qz[u], cd.z, cd.w)));
            net3(sa, a0[u], a1[u], a2[u]);
            net3(sb, a0[u], a1[u], a2[u]);
            net3(sc, a0[u], a1[u], a2[u]);
            net3(sd, a0[u], a1[u], a2[u]);
        }
    }
    // publish per-seg top-3 values
#pragma unroll
    for (int u = 0; u < 2; ++u) {
        int qq = qg * 2 + u;
        ms[(seg * 3 + 0) * 64 + qq] = a0[u];
        ms[(seg * 3 + 1) * 64 + qq] = a1[u];
        ms[(seg * 3 + 2) * 64 + qq] = a2[u];
    }
    __syncthreads();

    // global 3rd-largest value = threshold
    if (tid < 64) {
        float e0 = -3.4e38f, e1 = -3.4e38f, e2 = -3.4e38f;
#pragma unroll
        for (int sg = 0; sg < 8; ++sg) {
            net3(ms[(sg * 3 + 0) * 64 + tid], e0, e1, e2);
            net3(ms[(sg * 3 + 1) * 64 + tid], e0, e1, e2);
            net3(ms[(sg * 3 + 2) * 64 + tid], e0, e1, e2);
        }
        thr[tid] = e2;
    }
    __syncthreads();

    // -------- pass 2: collect indices of candidates with s >= threshold
    float th[2];
#pragma unroll
    for (int u = 0; u < 2; ++u) th[u] = thr[qg * 2 + u];

    float s0[2], s1[2], s2v[2];
    int i0[2], i1[2], i2[2];
#pragma unroll
    for (int u = 0; u < 2; ++u) {
        s0[u] = -3.4e38f; s1[u] = -3.4e38f; s2v[u] = -3.4e38f;
        i0[u] = 0; i1[u] = 0; i2[u] = 0;
    }

    for (int j = 0; j < 512; j += 4) {
        float4 ca = cand[j], cb = cand[j + 1], cc = cand[j + 2], cd = cand[j + 3];
#pragma unroll
        for (int u = 0; u < 2; ++u) {
            float sa = fmaf(qx[u], ca.x, fmaf(qy[u], ca.y, fmaf(qz[u], ca.z, ca.w)));
            float sb = fmaf(qx[u], cb.x, fmaf(qy[u], cb.y, fmaf(qz[u], cb.z, cb.w)));
            float sc = fmaf(qx[u], cc.x, fmaf(qy[u], cc.y, fmaf(qz[u], cc.z, cc.w)));
            float sd = fmaf(qx[u], cd.x, fmaf(qy[u], cd.y, fmaf(qz[u], cd.z, cd.w)));
            float m = fmaxf(fmaxf(sa, sb), fmaxf(sc, sd));
            if (m >= th[u]) {   // rare: gated by final global threshold
                insert3max(sa, sbase + j,     s0[u], s1[u], s2v[u], i0[u], i1[u], i2[u]);
                insert3max(sb, sbase + j + 1, s0[u], s1[u], s2v[u], i0[u], i1[u], i2[u]);
                insert3max(sc, sbase + j + 2, s0[u], s1[u], s2v[u], i0[u], i1[u], i2[u]);
                insert3max(sd, sbase + j + 3, s0[u], s1[u], s2v[u], i0[u], i1[u], i2[u]);
            }
        }
    }
    __syncthreads();   // ms reads in threshold stage done; safe to overwrite
#pragma unroll
    for (int u = 0; u < 2; ++u) {
        int qq = qg * 2 + u;
        ms[(seg * 3 + 0) * 64 + qq] = s0[u]; mx[(seg * 3 + 0) * 64 + qq] = i0[u];
        ms[(seg * 3 + 1) * 64 + qq] = s1[u]; mx[(seg * 3 + 1) * 64 + qq] = i1[u];
        ms[(seg * 3 + 2) * 64 + qq] = s2v[u]; mx[(seg * 3 + 2) * 64 + qq] = i2[u];
    }
    __syncthreads();

    // final merge (ascending seg order preserves tie behavior)
    if (tid < 64) {
        const int qq = tid;
        float e0 = -3.4e38f, e1 = -3.4e38f, e2 = -3.4e38f;
        int j0 = 0, j1 = 0, j2 = 0;
#pragma unroll
        for (int sg = 0; sg < 8; ++sg)
#pragma unroll
            for (int k = 0; k < 3; ++k)
                insert3max(ms[(sg * 3 + k) * 64 + qq], mx[(sg * 3 + k) * 64 + qq],
                           e0, e1, e2, j0, j1, j2);
        const float* q = xyz1 + ((long)b * N_ + q0 + qq) * 3;
        float ax = q[0], ay = q[1], az = q[2];
        float sq1 = ax * ax + ay * ay + az * az;
        float f0 = sq1 - 2.0f * e0;
        float f1 = sq1 - 2.0f * e1;
        float f2 = sq1 - 2.0f * e2;
        float r0 = 1.0f / (f0 + 1e-8f);
        float r1 = 1.0f / (f1 + 1e-8f);
        float r2 = 1.0f / (f2 + 1e-8f);
        float rs = 1.0f / (r0 + r1 + r2);
        long base = ((long)b * N_ + q0 + qq) * 3;
        g_idx[base + 0] = j0; g_idx[base + 1] = j1; g_idx[base + 2] = j2;
        g_w[base + 0] = r0 * rs; g_w[base + 1] = r1 * rs; g_w[base + 2] = r2 * rs;
    }
}

// ---------------------------------------------------------------- GEMM building blocks
__device__ __forceinline__ void cvt_global_to_op64(const float* __restrict__ src, int ldf,
                                                   uint32_t sbase) {
    for (int idx = threadIdx.x; idx < 2048; idx += 256) {
        int row = idx >> 5, c4 = idx & 31;
        int k = c4 << 2;
        float4 v = *(const float4*)(src + (long)row * ldf + k);
        uint32_t h0, h1;
        CVT2(h0, v.x, v.y);
        CVT2(h1, v.z, v.w);
        float hx = __uint_as_float(h0 << 16), hy = __uint_as_float(h0 & 0xffff0000u);
        float hz = __uint_as_float(h1 << 16), hw = __uint_as_float(h1 & 0xffff0000u);
        uint32_t l0, l1;
        CVT2(l0, v.x - hx, v.y - hy);
        CVT2(l1, v.z - hz, v.w - hw);
        int ghi = k >> 3, glo = 16 + ghi;
        int inb = (k & 7) << 1;
        uint32_t rb = sbase + row * 512;
        uint32_t ahi = rb + (((ghi ^ (row & 7)) << 4) | inb);
        uint32_t alo = rb + (((glo ^ (row & 7)) << 4) | inb);
        asm volatile("st.shared.v2.b32 [%0], {%1, %2};" :: "r"(ahi), "r"(h0), "r"(h1));
        asm volatile("st.shared.v2.b32 [%0], {%1, %2};" :: "r"(alo), "r"(l0), "r"(l1));
    }
}

__device__ __forceinline__ void mma_layer(uint32_t aop, const uint32_t* __restrict__ frag,
                                          float acc[2][4][4], int wm, int wn, int lane) {
    const int arow_in = (lane & 7) + ((lane >> 3) & 1) * 8;
    const int agsel = lane >> 4;
    const int fbase = (wn * 4) * 64 + lane * 2;
#pragma unroll
    for (int ksg = 0; ksg < 8; ++ksg) {
        uint2 bh[4], bl[4];
#pragma unroll
        for (int nt = 0; nt < 4; ++nt) {
            bh[nt] = *(const uint2*)(frag + ksg * 1024 + fbase + nt * 64);
            bl[nt] = *(const uint2*)(frag + 8192 + ksg * 1024 + fbase + nt * 64);
        }
        const int gAh = ksg * 2 + agsel;
        const int gAl = 16 + gAh;
        uint32_t aH[2][4], aL[2][4];
#pragma unroll
        for (int mt = 0; mt < 2; ++mt) {
            int row = wm * 32 + mt * 16 + arow_in;
            uint32_t rb = aop + row * 512;
            LDSM_X4(aH[mt][0], aH[mt][1], aH[mt][2], aH[mt][3],
                    rb + ((gAh ^ (row & 7)) << 4));
            LDSM_X4(aL[mt][0], aL[mt][1], aL[mt][2], aL[mt][3],
                    rb + ((gAl ^ (row & 7)) << 4));
        }
#pragma unroll
        for (int mt = 0; mt < 2; ++mt)
#pragma unroll
            for (int nt = 0; nt < 4; ++nt) {
                MMA16816(acc[mt][nt][0], acc[mt][nt][1], acc[mt][nt][2], acc[mt][nt][3],
                         aH[mt][0], aH[mt][1], aH[mt][2], aH[mt][3],
                         bh[nt].x, bh[nt].y);
                MMA16816(acc[mt][nt][0], acc[mt][nt][1], acc[mt][nt][2], acc[mt][nt][3],
                         aH[mt][0], aH[mt][1], aH[mt][2], aH[mt][3],
                         bl[nt].x, bl[nt].y);
                MMA16816(acc[mt][nt][0], acc[mt][nt][1], acc[mt][nt][2], acc[mt][nt][3],
                         aL[mt][0], aL[mt][1], aL[mt][2], aL[mt][3],
                         bh[nt].x, bh[nt].y);
            }
    }
}

__device__ __forceinline__ void epi_store(uint32_t aop, float v[2][4][4],
                                          int wm, int wn, int lane) {
    const int j = lane >> 3;
    const int rr = lane & 7;
#pragma unroll
    for (int mt = 0; mt < 2; ++mt)
#pragma unroll
        for (int np = 0; np < 2; ++np) {
            uint32_t h[4], l[4];
#pragma unroll
            for (int q = 0; q < 4; ++q) {
                int nt = np * 2 + (q >> 1);
                int base = (q & 1) * 2;
                float va = v[mt][nt][base], vb = v[mt][nt][base + 1];
                CVT2(h[q], va, vb);
                float la = va - __uint_as_float(h[q] << 16);
                float lb = vb - __uint_as_float(h[q] & 0xffff0000u);
                CVT2(l[q], la, lb);
            }
            int nt_j = np * 2 + (j >> 1);
            int grow = wm * 32 + mt * 16 + (j & 1) * 8 + rr;
            int gh = wn * 4 + nt_j;
            uint32_t ah = aop + grow * 512 + ((gh ^ (grow & 7)) << 4);
            uint32_t al = aop + grow * 512 + (((16 + gh) ^ (grow & 7)) << 4);
            STSM_X4(ah, h[0], h[1], h[2], h[3]);
            STSM_X4(al, l[0], l[1], l[2], l[3]);
        }
}

__device__ __forceinline__ void zero_acc4(float acc[2][4][4]) {
#pragma unroll
    for (int mt = 0; mt < 2; ++mt)
#pragma unroll
        for (int nt = 0; nt < 4; ++nt)
#pragma unroll
            for (int j = 0; j < 4; ++j) acc[mt][nt][j] = 0.f;
}

__device__ __forceinline__ void store_acc_to_D(float* Df, float acc[2][4][4],
                                               int wm, int wn, int lane) {
    const int r = lane >> 2;
    const int c2 = (lane & 3) * 2;
#pragma unroll
    for (int mt = 0; mt < 2; ++mt)
#pragma unroll
        for (int nt = 0; nt < 4; ++nt) {
            int m = wm * 32 + mt * 16 + r;
            int n = wn * 32 + nt * 8 + c2;
            *(float2*)(Df + m * DPITCH + n) = make_float2(acc[mt][nt][0], acc[mt][nt][1]);
            *(float2*)(Df + (m + 8) * DPITCH + n) = make_float2(acc[mt][nt][2], acc[mt][nt][3]);
        }
}

// ---------------------------------------------------------------- ZY kernel
__global__ void __launch_bounds__(256, 2) zy_kernel(const float* __restrict__ last_pred) {
    extern __shared__ char smem[];
    const uint32_t sb = smem_u32(smem);
    const int tid = threadIdx.x;
    const int wid = tid >> 5;
    const int lane = tid & 31;
    const int wm = wid >> 2;
    const int wn = wid & 3;
    const int b = blockIdx.y;
    const int s0 = blockIdx.x * 64;

    float* w3f = (float*)(smem + SM_WP2);
    for (int i = tid; i < 128 * NCLS; i += 256) w3f[i] = g_W3f[i];

    float acc[2][4][4];
    zero_acc4(acc);
#pragma unroll
    for (int slice = 0; slice < 2; ++slice) {
        cvt_global_to_op64(g_p2T + ((long)b * S_ + s0) * 256 + slice * 128, 256, sb + SM_AOP);
        __syncthreads();
        mma_layer(sb + SM_AOP, g_Wfrag[1 + slice], acc, wm, wn, lane);
        __syncthreads();
    }
    float* Df = (float*)(smem + SM_D);
    store_acc_to_D(Df, acc, wm, wn, lane);
    __syncthreads();

    const int p = tid >> 2;
    const int ch = (tid & 3) * 32;
    const int s = s0 + p;
    const float* srow = Df + p * DPITCH + ch;
    float v[32];
#pragma unroll
    for (int j = 0; j < 32; j += 4) {
        float4 t = *(const float4*)(srow + j);
        v[j] = t.x; v[j + 1] = t.y; v[j + 2] = t.z; v[j + 3] = t.w;
    }
    const float* lpp = last_pred + ((long)b * S_ + s) * NCLS;
    float lp[NCLS];
#pragma unroll
    for (int j = 0; j < NCLS; ++j) lp[j] = lpp[j];
#pragma unroll
    for (int c = 0; c < 32; ++c) {
        const float* wr = w3f + (ch + c) * NCLS;
        float a = 0.f;
#pragma unroll
        for (int j = 0; j < NCLS; ++j) a = fmaf(wr[j], lp[j], a);
        v[c] += a;
    }
    float* zrow = g_ZY + ((long)b * S_ + s) * 128 + ch;
#pragma unroll
    for (int j = 0; j < 32; j += 4)
        *(float4*)(zrow + j) = make_float4(v[j], v[j + 1], v[j + 2], v[j + 3]);
}

// ---------------------------------------------------------------- MEGA kernel (grid = (N/64, B))
__global__ void __launch_bounds__(256, 2) mega_kernel(float* __restrict__ out) {
    extern __shared__ char smem[];
    const uint32_t sb = smem_u32(smem);
    const int tid = threadIdx.x;
    const int wid = tid >> 5;
    const int lane = tid & 31;
    const int b = blockIdx.y;
    const int n0 = blockIdx.x * 64;

    const int wm = wid >> 2;
    const int wn = wid & 3;
    const int r = lane >> 2;
    const int c2 = (lane & 3) * 2;

    float* biasArr = (float*)(smem + SM_BIAS);
    for (int i = tid; i < 512; i += 256) {
        int which = i >> 7, c = i & 127;
        float v;
        if (which == 0) v = g_bfuse[c];
        else if (which == 1) v = g_be1[c];
        else if (which == 2) v = g_be2[c];
        else v = g_bp1[c];
        biasArr[i] = v;
    }
    float* bp2s = (float*)(smem + SM_BP2);
    if (tid < NCLS) bp2s[tid] = g_bp2[tid];
    float* wp2s = (float*)(smem + SM_WP2);
    for (int i = tid; i < NCLS * 128; i += 256) wp2s[i] = g_Wp2[i];

    float* Df = (float*)(smem + SM_D);
    float acc[2][4][4];
    float resid[2][4][4];

    // ---------------- L0: fuse
    cvt_global_to_op64(g_p1T + ((long)b * N_ + n0) * 128, 128, sb + SM_AOP);
    __syncthreads();
    zero_acc4(acc);
    mma_layer(sb + SM_AOP, g_Wfrag[0], acc, wm, wn, lane);
    __syncthreads();
    {
        float b0v[4], b1v[4];
#pragma unroll
        for (int nt = 0; nt < 4; ++nt) {
            int c = wn * 32 + nt * 8 + c2;
            b0v[nt] = biasArr[c];
            b1v[nt] = biasArr[c + 1];
        }
#pragma unroll
        for (int mt = 0; mt < 2; ++mt) {
#pragma unroll
            for (int half = 0; half < 2; ++half) {
                int row = wm * 32 + mt * 16 + half * 8 + r;
                long gb = ((long)b * N_ + n0 + row) * 3;
                int i0 = g_idx[gb], i1 = g_idx[gb + 1], i2 = g_idx[gb + 2];
                float w0 = g_w[gb], w1 = g_w[gb + 1], w2 = g_w[gb + 2];
                const float* z0 = g_ZY + ((long)b * S_ + i0) * 128;
                const float* z1 = g_ZY + ((long)b * S_ + i1) * 128;
                const float* z2 = g_ZY + ((long)b * S_ + i2) * 128;
#pragma unroll
                for (int nt = 0; nt < 4; ++nt) {
                    int c = wn * 32 + nt * 8 + c2;
                    float2 a0 = *(const float2*)(z0 + c);
                    float2 a1 = *(const float2*)(z1 + c);
                    float2 a2 = *(const float2*)(z2 + c);
                    float v0 = acc[mt][nt][half * 2 + 0] + b0v[nt]
                             + w0 * a0.x + w1 * a1.x + w2 * a2.x;
                    float v1 = acc[mt][nt][half * 2 + 1] + b1v[nt]
                             + w0 * a0.y + w1 * a1.y + w2 * a2.y;
                    v0 = fmaxf(v0, 0.f);
                    v1 = fmaxf(v1, 0.f);
                    acc[mt][nt][half * 2 + 0] = v0;
                    acc[mt][nt][half * 2 + 1] = v1;
                    resid[mt][nt][half * 2 + 0] = v0;
                    resid[mt][nt][half * 2 + 1] = v1;
                }
            }
        }
        epi_store(sb + SM_AOP, acc, wm, wn, lane);
    }
    __syncthreads();

    // ---------------- L1: ext1
    zero_acc4(acc);
    mma_layer(sb + SM_AOP, g_Wfrag[3], acc, wm, wn, lane);
    __syncthreads();
    {
#pragma unroll
        for (int mt = 0; mt < 2; ++mt)
#pragma unroll
            for (int nt = 0; nt < 4; ++nt) {
                int c = wn * 32 + nt * 8 + c2;
                acc[mt][nt][0] = fmaxf(acc[mt][nt][0] + biasArr[128 + c], 0.f);
                acc[mt][nt][1] = fmaxf(acc[mt][nt][1] + biasArr[128 + c + 1], 0.f);
                acc[mt][nt][2] = fmaxf(acc[mt][nt][2] + biasArr[128 + c], 0.f);
                acc[mt][nt][3] = fmaxf(acc[mt][nt][3] + biasArr[128 + c + 1], 0.f);
            }
        epi_store(sb + SM_AOP, acc, wm, wn, lane);
    }
    __syncthreads();

    // ---------------- L2: ext2 + residual
    zero_acc4(acc);
    mma_layer(sb + SM_AOP, g_Wfrag[4], acc, wm, wn, lane);
    __syncthreads();
    {
#pragma unroll
        for (int mt = 0; mt < 2; ++mt)
#pragma unroll
            for (int nt = 0; nt < 4; ++nt) {
                int c = wn * 32 + nt * 8 + c2;
                acc[mt][nt][0] = fmaxf(acc[mt][nt][0] + biasArr[256 + c] + resid[mt][nt][0], 0.f);
                acc[mt][nt][1] = fmaxf(acc[mt][nt][1] + biasArr[256 + c + 1] + resid[mt][nt][1], 0.f);
                acc[mt][nt][2] = fmaxf(acc[mt][nt][2] + biasArr[256 + c] + resid[mt][nt][2], 0.f);
                acc[mt][nt][3] = fmaxf(acc[mt][nt][3] + biasArr[256 + c + 1] + resid[mt][nt][3], 0.f);
            }
        epi_store(sb + SM_AOP, acc, wm, wn, lane);
        store_acc_to_D(Df, acc, wm, wn, lane);
    }
    __syncthreads();
    {
        float* o0 = out + OUT0_OFF + (long)b * 128 * N_ + n0;
        for (int c = wid; c < 128; c += 8) {
            float* dstc = o0 + (long)c * N_;
            for (int p = lane; p < 64; p += 32) dstc[p] = Df[p * DPITCH + c];
        }
    }

    // ---------------- L3: pred1
    zero_acc4(acc);
    mma_layer(sb + SM_AOP, g_Wfrag[5], acc, wm, wn, lane);
    __syncthreads();
    {
#pragma unroll
        for (int mt = 0; mt < 2; ++mt)
#pragma unroll
            for (int nt = 0; nt < 4; ++nt) {
                int c = wn * 32 + nt * 8 + c2;
                acc[mt][nt][0] = fmaxf(acc[mt][nt][0] + biasArr[384 + c], 0.f);
                acc[mt][nt][1] = fmaxf(acc[mt][nt][1] + biasArr[384 + c + 1], 0.f);
                acc[mt][nt][2] = fmaxf(acc[mt][nt][2] + biasArr[384 + c], 0.f);
                acc[mt][nt][3] = fmaxf(acc[mt][nt][3] + biasArr[384 + c + 1], 0.f);
            }
        store_acc_to_D(Df, acc, wm, wn, lane);
    }
    __syncthreads();

    {
        float* o1 = out + OUT1_OFF + ((long)b * N_ + n0) * 128;
        for (int idx = tid; idx < 2048; idx += 256) {
            int row = idx >> 5, c4 = idx & 31;
            float4 t = *(const float4*)(Df + row * DPITCH + c4 * 4);
            *(float4*)(o1 + row * 128 + c4 * 4) = t;
        }
    }
    for (int o = tid; o < 64 * NCLS; o += 256) {
        int pp = o / NCLS, j = o - pp * NCLS;
        const float* fr = Df + pp * DPITCH;
        const float* wr = wp2s + j * 128;
        float a = bp2s[j];
#pragma unroll 16
        for (int k = 0; k < 128; ++k) a = fmaf(fr[k], wr[k], a);
        out[OUT2_OFF + ((long)b * N_ + n0 + pp) * NCLS + j] = fmaxf(a, 0.f);
    }
}

// ---------------------------------------------------------------- launch
extern "C" void kernel_launch(void* const* d_in, const int* in_sizes, int n_in,
                              void* d_out, int out_size) {
    const float* xyz1      = (const float*)d_in[0];
    const float* xyz2      = (const float*)d_in[1];
    const float* points1   = (const float*)d_in[2];
    const float* points2   = (const float*)d_in[3];
    const float* last_pred = (const float*)d_in[4];
    const float* fuse_W = (const float*)d_in[5];
    const float* fuse_b = (const float*)d_in[6];
    const float* fuse_bn = (const float*)d_in[7];
    const float* e1_W = (const float*)d_in[8];
    const float* e1_b = (const float*)d_in[9];
    const float* e1_bn = (const float*)d_in[10];
    const float* e2_W = (const float*)d_in[11];
    const float* e2_b = (const float*)d_in[12];
    const float* e2_bn = (const float*)d_in[13];
    const float* p1_W = (const float*)d_in[14];
    const float* p1_b = (const float*)d_in[15];
    const float* p1_bn = (const float*)d_in[16];
    const float* p2_W = (const float*)d_in[17];
    const float* p2_b = (const float*)d_in[18];
    const float* p2_bn = (const float*)d_in[19];

    float* out = (float*)d_out;

    cudaFuncSetAttribute(zy_kernel, cudaFuncAttributeMaxDynamicSharedMemorySize, SM_TOT);
    cudaFuncSetAttribute(mega_kernel, cudaFuncAttributeMaxDynamicSharedMemorySize, SM_TOT);

    // [0] prep: weights + candidate packing
    prep_kernel<<<PREP_BLOCKS, 256>>>(
        xyz2,
        fuse_W, fuse_b, fuse_bn, e1_W, e1_b, e1_bn,
        e2_W, e2_b, e2_bn, p1_W, p1_b, p1_bn, p2_W, p2_b, p2_bn);
    // [1] both transposes
    transpose_both<<<6144, 256>>>(points1, points2);
    // [2] ZY
    {
        dim3 grid(S_ / 64, B_);
        zy_kernel<<<grid, 256, SM_TOT>>>(last_pred);
    }
    // [3] top3 (profiled launch)
    top3_kernel<<<512, 256>>>(xyz1);
    // [4] mega
    {
        dim3 grid(N_ / 64, B_);
        mega_kernel<<<grid, 256, SM_TOT>>>(out);
    }
}

// round 14
// speedup vs baseline: 1.1343x; 1.1343x over previous
#include <cuda_runtime.h>
#include <cuda_bf16.h>
#include <math.h>
#include <stdint.h>

// ---------------------------------------------------------------- constants
#define B_    2
#define N_    16384
#define S_    4096
#define D1_   128
#define D2_   256
#define CIN_  397
#define C_    128
#define NCLS  13

#define OUT0_OFF 0
#define OUT1_OFF (B_ * C_ * N_)
#define OUT2_OFF (OUT1_OFF + B_ * N_ * C_)

// ---------------------------------------------------------------- scratch
__device__ uint32_t g_Wfrag[6][16384];   // lane-ordered MMA B fragments
__device__ float g_bfuse[C_];
__device__ float g_be1[C_];
__device__ float g_be2[C_];
__device__ float g_bp1[C_];
__device__ float g_Wp2[NCLS * C_];
__device__ float g_bp2[NCLS];
__device__ float g_W3f[C_ * NCLS];
__device__ float g_ZY[B_ * S_ * C_];
__device__ int   g_idx[B_ * N_ * 3];
__device__ float g_w[B_ * N_ * 3];
__device__ float g_p1T[B_ * N_ * D1_];
__device__ float g_p2T[B_ * S_ * D2_];

// ---------------------------------------------------------------- helpers
__device__ __forceinline__ uint32_t smem_u32(const void* p) {
    uint32_t a;
    asm("{ .reg .u64 t; cvta.to.shared.u64 t, %1; cvt.u32.u64 %0, t; }"
        : "=r"(a) : "l"(p));
    return a;
}

#define CVT2(res, a, b) \
    asm("cvt.rn.satfinite.bf16x2.f32 %0, %1, %2;" : "=r"(res) : "f"(b), "f"(a))

#define LDSM_X4(r0, r1, r2, r3, addr) \
    asm volatile("ldmatrix.sync.aligned.m8n8.x4.shared.b16 {%0,%1,%2,%3}, [%4];" \
                 : "=r"(r0), "=r"(r1), "=r"(r2), "=r"(r3) : "r"(addr))

#define STSM_X4(addr, r0, r1, r2, r3) \
    asm volatile("stmatrix.sync.aligned.m8n8.x4.shared.b16 [%0], {%1,%2,%3,%4};" \
                 :: "r"(addr), "r"(r0), "r"(r1), "r"(r2), "r"(r3))

#define MMA16816(c0, c1, c2, c3, a0, a1, a2, a3, b0, b1) \
    asm volatile("mma.sync.aligned.m16n8k16.row.col.f32.bf16.bf16.f32 " \
                 "{%0,%1,%2,%3}, {%4,%5,%6,%7}, {%8,%9}, {%0,%1,%2,%3};" \
                 : "+f"(c0), "+f"(c1), "+f"(c2), "+f"(c3) \
                 : "r"(a0), "r"(a1), "r"(a2), "r"(a3), "r"(b0), "r"(b1))

// ---------------------------------------------------------------- smem layout (bytes) for GEMM kernels
#define SM_BIAS 0
#define SM_BP2  2048
#define SM_WP2  2112
#define SM_AOP  9216                     // 32768: A tile 64 rows x 512B
#define SM_D    (9216 + 32768)           // fp32 D 64 x 132 = 33792
#define SM_TOT  (41984 + 33792)          // 75776
#define DPITCH  132

// front kernel block ranges
#define TOP3_BLOCKS 512
#define PREP_BLOCKS 112
#define TRANS_BLOCKS 6144
#define FRONT_BLOCKS (TOP3_BLOCKS + PREP_BLOCKS + TRANS_BLOCKS)
// front smem: candidate tile 4096 float4 = 65536, merge md 3072, mi 3072
#define FR_TOT (65536 + 6144)

// ---------------------------------------------------------------- fold helpers
__device__ __forceinline__ float fold_scale(const float* bn, int Cout, int o) {
    return bn[o] * rsqrtf(bn[3 * Cout + o] + 1e-5f);
}

// keep top-3 LARGEST s; strict > keeps earlier index on ties
__device__ __forceinline__ void insert3max(float s, int si,
                                           float& s0, float& s1, float& s2,
                                           int& i0, int& i1, int& i2) {
    if (s > s2) {
        if (s > s1) {
            s2 = s1; i2 = i1;
            if (s > s0) { s1 = s0; i1 = i0; s0 = s; i0 = si; }
            else        { s1 = s;  i1 = si; }
        } else { s2 = s; i2 = si; }
    }
}

// ---------------------------------------------------------------- front: top3 + prep + transposes
__global__ void __launch_bounds__(256) front_kernel(
    const float* __restrict__ xyz1, const float* __restrict__ xyz2,
    const float* __restrict__ p1, const float* __restrict__ p2,
    const float* __restrict__ fW, const float* __restrict__ fb, const float* __restrict__ fbn,
    const float* __restrict__ e1W, const float* __restrict__ e1b, const float* __restrict__ e1bn,
    const float* __restrict__ e2W, const float* __restrict__ e2b, const float* __restrict__ e2bn,
    const float* __restrict__ p1W, const float* __restrict__ p1b, const float* __restrict__ p1bn,
    const float* __restrict__ p2W, const float* __restrict__ p2b, const float* __restrict__ p2bn) {
    extern __shared__ char smem[];
    const int tid = threadIdx.x;

    if (blockIdx.x < TOP3_BLOCKS) {
        // ---------------- top3: 64 queries/block, 4 segs x 1024 cands, smem-staged
        float4* tile = (float4*)smem;
        float* md = (float*)(smem + 65536);
        int* mi = (int*)(smem + 65536 + 3072);
        const int blk = blockIdx.x;
        const int b = blk >> 8;
        const int q0 = (blk & 255) * 64;
        const int ql = tid & 63;
        const int seg = tid >> 6;             // 0..3

        // stage all 4096 candidates, packed (x, y, z, -0.5|c|^2)
        for (int t = tid; t < S_; t += 256) {
            const float* p = xyz2 + ((long)b * S_ + t) * 3;
            float x = p[0], y = p[1], z = p[2];
            tile[t] = make_float4(x, y, z, -0.5f * (x * x + y * y + z * z));
        }
        __syncthreads();

        const int n = q0 + ql;
        const float* q = xyz1 + ((long)b * N_ + n) * 3;
        const float qx = q[0], qy = q[1], qz = q[2];

        float s0 = -3.4e38f, s1 = -3.4e38f, s2 = -3.4e38f;
        int i0 = 0, i1 = 0, i2 = 0;
        const float4* cand = tile + seg * 1024;
        const int sbase = seg * 1024;

#pragma unroll 4
        for (int j = 0; j < 1024; j += 4) {
            float4 ca = cand[j], cb = cand[j + 1], cc = cand[j + 2], cd = cand[j + 3];
            float sa = fmaf(qx, ca.x, fmaf(qy, ca.y, fmaf(qz, ca.z, ca.w)));
            float sb = fmaf(qx, cb.x, fmaf(qy, cb.y, fmaf(qz, cb.z, cb.w)));
            float sc = fmaf(qx, cc.x, fmaf(qy, cc.y, fmaf(qz, cc.z, cc.w)));
            float sd = fmaf(qx, cd.x, fmaf(qy, cd.y, fmaf(qz, cd.z, cd.w)));
            float m = fmaxf(fmaxf(sa, sb), fmaxf(sc, sd));
            if (m > s2) {
                insert3max(sa, sbase + j,     s0, s1, s2, i0, i1, i2);
                insert3max(sb, sbase + j + 1, s0, s1, s2, i0, i1, i2);
                insert3max(sc, sbase + j + 2, s0, s1, s2, i0, i1, i2);
                insert3max(sd, sbase + j + 3, s0, s1, s2, i0, i1, i2);
            }
        }

        md[(seg * 3 + 0) * 64 + ql] = s0; mi[(seg * 3 + 0) * 64 + ql] = i0;
        md[(seg * 3 + 1) * 64 + ql] = s1; mi[(seg * 3 + 1) * 64 + ql] = i1;
        md[(seg * 3 + 2) * 64 + ql] = s2; mi[(seg * 3 + 2) * 64 + ql] = i2;
        __syncthreads();

        if (seg == 0) {
            float e0 = -3.4e38f, e1 = -3.4e38f, e2 = -3.4e38f;
            int j0 = 0, j1 = 0, j2 = 0;
#pragma unroll
            for (int sg = 0; sg < 4; ++sg)
#pragma unroll
                for (int k = 0; k < 3; ++k)
                    insert3max(md[(sg * 3 + k) * 64 + ql], mi[(sg * 3 + k) * 64 + ql],
                               e0, e1, e2, j0, j1, j2);
            float sq1 = qx * qx + qy * qy + qz * qz;
            float f0 = sq1 - 2.0f * e0;
            float f1 = sq1 - 2.0f * e1;
            float f2 = sq1 - 2.0f * e2;
            float r0 = 1.0f / (f0 + 1e-8f);
            float r1 = 1.0f / (f1 + 1e-8f);
            float r2 = 1.0f / (f2 + 1e-8f);
            float rs = 1.0f / (r0 + r1 + r2);
            long base = ((long)b * N_ + n) * 3;
            g_idx[base + 0] = j0; g_idx[base + 1] = j1; g_idx[base + 2] = j2;
            g_w[base + 0] = r0 * rs; g_w[base + 1] = r1 * rs; g_w[base + 2] = r2 * rs;
        }
    } else if (blockIdx.x < TOP3_BLOCKS + PREP_BLOCKS) {
        // ---------------- prep: fold + fragment-convert all weights/biases
        const int FRAG_END = 6 * 8 * 16 * 32;   // 24576
        const int BIAS_END = FRAG_END + 512;
        const int BP2_END = BIAS_END + NCLS;
        const int WP2_END = BP2_END + NCLS * 128;
        const int W3F_END = WP2_END + 128 * NCLS;
        const int pb = blockIdx.x - TOP3_BLOCKS;
        for (int i = pb * 256 + tid; i < W3F_END; i += PREP_BLOCKS * 256) {
            if (i < FRAG_END) {
                int t = i >> 12;
                int rem = i & 4095;
                int ksg = rem >> 9;
                int nblk = (rem >> 5) & 15;
                int lane = rem & 31;
                int n = nblk * 8 + (lane >> 2);
                int k = ksg * 16 + ((lane & 3) << 1);
                const float* src;
                int ld;
                float s;
                if (t == 0)      { src = fW;        ld = CIN_; s = fold_scale(fbn, 128, n); }
                else if (t == 1) { src = fW + 128;  ld = CIN_; s = fold_scale(fbn, 128, n); }
                else if (t == 2) { src = fW + 256;  ld = CIN_; s = fold_scale(fbn, 128, n); }
                else if (t == 3) { src = e1W;       ld = 128;  s = fold_scale(e1bn, 128, n); }
                else if (t == 4) { src = e2W;       ld = 128;  s = fold_scale(e2bn, 128, n); }
                else             { src = p1W;       ld = 128;  s = fold_scale(p1bn, 128, n); }
                const float* rowp = src + (long)n * ld + k;
                float w0 = rowp[0] * s, w1 = rowp[1] * s;
                float w8 = rowp[8] * s, w9 = rowp[9] * s;
                uint32_t h0, h1;
                CVT2(h0, w0, w1);
                CVT2(h1, w8, w9);
                float l0a = w0 - __uint_as_float(h0 << 16);
                float l0b = w1 - __uint_as_float(h0 & 0xffff0000u);
                float l1a = w8 - __uint_as_float(h1 << 16);
                float l1b = w9 - __uint_as_float(h1 & 0xffff0000u);
                uint32_t lo0, lo1;
                CVT2(lo0, l0a, l0b);
                CVT2(lo1, l1a, l1b);
                int off = ksg * 1024 + nblk * 64 + lane * 2;
                g_Wfrag[t][off + 0] = h0;
                g_Wfrag[t][off + 1] = h1;
                g_Wfrag[t][8192 + off + 0] = lo0;
                g_Wfrag[t][8192 + off + 1] = lo1;
            } else if (i < BIAS_END) {
                int j = i - FRAG_END;
                int which = j >> 7, c = j & 127;
                const float *b, *bn;
                float* dst;
                if (which == 0)      { b = fb;  bn = fbn;  dst = g_bfuse; }
                else if (which == 1) { b = e1b; bn = e1bn; dst = g_be1; }
                else if (which == 2) { b = e2b; bn = e2bn; dst = g_be2; }
                else                 { b = p1b; bn = p1bn; dst = g_bp1; }
                float s = fold_scale(bn, 128, c);
                dst[c] = (b[c] - bn[2 * 128 + c]) * s + bn[128 + c];
            } else if (i < BP2_END) {
                int o = i - BIAS_END;
                float s = fold_scale(p2bn, NCLS, o);
                g_bp2[o] = (p2b[o] - p2bn[2 * NCLS + o]) * s + p2bn[NCLS + o];
            } else if (i < WP2_END) {
                int j = i - BP2_END;
                int o = j >> 7;
                float s = fold_scale(p2bn, NCLS, o);
                g_Wp2[j] = p2W[j] * s;
            } else {
                int j = i - WP2_END;
                int o = j / NCLS;
                float s = fold_scale(fbn, 128, o);
                g_W3f[j] = fW[o * CIN_ + 384 + (j - o * NCLS)] * s;
            }
        }
    } else {
        // ---------------- transpose (flat 256 threads)
        float (*t)[33] = (float(*)[33])smem;
        const int tx = tid & 31;
        const int ty = tid >> 5;
        const int local0 = blockIdx.x - TOP3_BLOCKS - PREP_BLOCKS;
        const float* src;
        float* dst;
        int C, Nn, n0, c0, b;
        if (local0 < 4096) {
            b = local0 >> 11;
            int rem = local0 & 2047;
            c0 = (rem >> 9) * 32;
            n0 = (rem & 511) * 32;
            C = 128; Nn = N_;
            src = p1; dst = g_p1T;
        } else {
            int local = local0 - 4096;
            b = local >> 10;
            int rem = local & 1023;
            c0 = (rem >> 7) * 32;
            n0 = (rem & 127) * 32;
            C = 256; Nn = S_;
            src = p2; dst = g_p2T;
        }
        const float* s = src + (long)b * C * Nn;
        float* d = dst + (long)b * Nn * C;
        for (int i = ty; i < 32; i += 8)
            t[i][tx] = s[(long)(c0 + i) * Nn + n0 + tx];
        __syncthreads();
        for (int i = ty; i < 32; i += 8)
            d[(long)(n0 + i) * C + c0 + tx] = t[tx][i];
    }
}

// ---------------------------------------------------------------- GEMM building blocks
__device__ __forceinline__ void cvt_global_to_op64(const float* __restrict__ src, int ldf,
                                                   uint32_t sbase) {
    for (int idx = threadIdx.x; idx < 2048; idx += 256) {
        int row = idx >> 5, c4 = idx & 31;
        int k = c4 << 2;
        float4 v = *(const float4*)(src + (long)row * ldf + k);
        uint32_t h0, h1;
        CVT2(h0, v.x, v.y);
        CVT2(h1, v.z, v.w);
        float hx = __uint_as_float(h0 << 16), hy = __uint_as_float(h0 & 0xffff0000u);
        float hz = __uint_as_float(h1 << 16), hw = __uint_as_float(h1 & 0xffff0000u);
        uint32_t l0, l1;
        CVT2(l0, v.x - hx, v.y - hy);
        CVT2(l1, v.z - hz, v.w - hw);
        int ghi = k >> 3, glo = 16 + ghi;
        int inb = (k & 7) << 1;
        uint32_t rb = sbase + row * 512;
        uint32_t ahi = rb + (((ghi ^ (row & 7)) << 4) | inb);
        uint32_t alo = rb + (((glo ^ (row & 7)) << 4) | inb);
        asm volatile("st.shared.v2.b32 [%0], {%1, %2};" :: "r"(ahi), "r"(h0), "r"(h1));
        asm volatile("st.shared.v2.b32 [%0], {%1, %2};" :: "r"(alo), "r"(l0), "r"(l1));
    }
}

__device__ __forceinline__ void mma_layer(uint32_t aop, const uint32_t* __restrict__ frag,
                                          float acc[2][4][4], int wm, int wn, int lane) {
    const int arow_in = (lane & 7) + ((lane >> 3) & 1) * 8;
    const int agsel = lane >> 4;
    const int fbase = (wn * 4) * 64 + lane * 2;
#pragma unroll
    for (int ksg = 0; ksg < 8; ++ksg) {
        uint2 bh[4], bl[4];
#pragma unroll
        for (int nt = 0; nt < 4; ++nt) {
            bh[nt] = *(const uint2*)(frag + ksg * 1024 + fbase + nt * 64);
            bl[nt] = *(const uint2*)(frag + 8192 + ksg * 1024 + fbase + nt * 64);
        }
        const int gAh = ksg * 2 + agsel;
        const int gAl = 16 + gAh;
        uint32_t aH[2][4], aL[2][4];
#pragma unroll
        for (int mt = 0; mt < 2; ++mt) {
            int row = wm * 32 + mt * 16 + arow_in;
            uint32_t rb = aop + row * 512;
            LDSM_X4(aH[mt][0], aH[mt][1], aH[mt][2], aH[mt][3],
                    rb + ((gAh ^ (row & 7)) << 4));
            LDSM_X4(aL[mt][0], aL[mt][1], aL[mt][2], aL[mt][3],
                    rb + ((gAl ^ (row & 7)) << 4));
        }
#pragma unroll
        for (int mt = 0; mt < 2; ++mt)
#pragma unroll
            for (int nt = 0; nt < 4; ++nt) {
                MMA16816(acc[mt][nt][0], acc[mt][nt][1], acc[mt][nt][2], acc[mt][nt][3],
                         aH[mt][0], aH[mt][1], aH[mt][2], aH[mt][3],
                         bh[nt].x, bh[nt].y);
                MMA16816(acc[mt][nt][0], acc[mt][nt][1], acc[mt][nt][2], acc[mt][nt][3],
                         aH[mt][0], aH[mt][1], aH[mt][2], aH[mt][3],
                         bl[nt].x, bl[nt].y);
                MMA16816(acc[mt][nt][0], acc[mt][nt][1], acc[mt][nt][2], acc[mt][nt][3],
                         aL[mt][0], aL[mt][1], aL[mt][2], aL[mt][3],
                         bh[nt].x, bh[nt].y);
            }
    }
}

__device__ __forceinline__ void epi_store(uint32_t aop, float v[2][4][4],
                                          int wm, int wn, int lane) {
    const int j = lane >> 3;
    const int rr = lane & 7;
#pragma unroll
    for (int mt = 0; mt < 2; ++mt)
#pragma unroll
        for (int np = 0; np < 2; ++np) {
            uint32_t h[4], l[4];
#pragma unroll
            for (int q = 0; q < 4; ++q) {
                int nt = np * 2 + (q >> 1);
                int base = (q & 1) * 2;
                float va = v[mt][nt][base], vb = v[mt][nt][base + 1];
                CVT2(h[q], va, vb);
                float la = va - __uint_as_float(h[q] << 16);
                float lb = vb - __uint_as_float(h[q] & 0xffff0000u);
                CVT2(l[q], la, lb);
            }
            int nt_j = np * 2 + (j >> 1);
            int grow = wm * 32 + mt * 16 + (j & 1) * 8 + rr;
            int gh = wn * 4 + nt_j;
            uint32_t ah = aop + grow * 512 + ((gh ^ (grow & 7)) << 4);
            uint32_t al = aop + grow * 512 + (((16 + gh) ^ (grow & 7)) << 4);
            STSM_X4(ah, h[0], h[1], h[2], h[3]);
            STSM_X4(al, l[0], l[1], l[2], l[3]);
        }
}

__device__ __forceinline__ void zero_acc4(float acc[2][4][4]) {
#pragma unroll
    for (int mt = 0; mt < 2; ++mt)
#pragma unroll
        for (int nt = 0; nt < 4; ++nt)
#pragma unroll
            for (int j = 0; j < 4; ++j) acc[mt][nt][j] = 0.f;
}

__device__ __forceinline__ void store_acc_to_D(float* Df, float acc[2][4][4],
                                               int wm, int wn, int lane) {
    const int r = lane >> 2;
    const int c2 = (lane & 3) * 2;
#pragma unroll
    for (int mt = 0; mt < 2; ++mt)
#pragma unroll
        for (int nt = 0; nt < 4; ++nt) {
            int m = wm * 32 + mt * 16 + r;
            int n = wn * 32 + nt * 8 + c2;
            *(float2*)(Df + m * DPITCH + n) = make_float2(acc[mt][nt][0], acc[mt][nt][1]);
            *(float2*)(Df + (m + 8) * DPITCH + n) = make_float2(acc[mt][nt][2], acc[mt][nt][3]);
        }
}

// ---------------------------------------------------------------- ZY kernel
__global__ void __launch_bounds__(256, 2) zy_kernel(const float* __restrict__ last_pred) {
    extern __shared__ char smem[];
    const uint32_t sb = smem_u32(smem);
    const int tid = threadIdx.x;
    const int wid = tid >> 5;
    const int lane = tid & 31;
    const int wm = wid >> 2;
    const int wn = wid & 3;
    const int b = blockIdx.y;
    const int s0 = blockIdx.x * 64;

    float* w3f = (float*)(smem + SM_WP2);
    for (int i = tid; i < 128 * NCLS; i += 256) w3f[i] = g_W3f[i];

    float acc[2][4][4];
    zero_acc4(acc);
#pragma unroll
    for (int slice = 0; slice < 2; ++slice) {
        cvt_global_to_op64(g_p2T + ((long)b * S_ + s0) * 256 + slice * 128, 256, sb + SM_AOP);
        __syncthreads();
        mma_layer(sb + SM_AOP, g_Wfrag[1 + slice], acc, wm, wn, lane);
        __syncthreads();
    }
    float* Df = (float*)(smem + SM_D);
    store_acc_to_D(Df, acc, wm, wn, lane);
    __syncthreads();

    const int p = tid >> 2;
    const int ch = (tid & 3) * 32;
    const int s = s0 + p;
    const float* srow = Df + p * DPITCH + ch;
    float v[32];
#pragma unroll
    for (int j = 0; j < 32; j += 4) {
        float4 t = *(const float4*)(srow + j);
        v[j] = t.x; v[j + 1] = t.y; v[j + 2] = t.z; v[j + 3] = t.w;
    }
    const float* lpp = last_pred + ((long)b * S_ + s) * NCLS;
    float lp[NCLS];
#pragma unroll
    for (int j = 0; j < NCLS; ++j) lp[j] = lpp[j];
#pragma unroll
    for (int c = 0; c < 32; ++c) {
        const float* wr = w3f + (ch + c) * NCLS;
        float a = 0.f;
#pragma unroll
        for (int j = 0; j < NCLS; ++j) a = fmaf(wr[j], lp[j], a);
        v[c] += a;
    }
    float* zrow = g_ZY + ((long)b * S_ + s) * 128 + ch;
#pragma unroll
    for (int j = 0; j < 32; j += 4)
        *(float4*)(zrow + j) = make_float4(v[j], v[j + 1], v[j + 2], v[j + 3]);
}

// ---------------------------------------------------------------- MEGA kernel (grid = (N/64, B))
__global__ void __launch_bounds__(256, 2) mega_kernel(float* __restrict__ out) {
    extern __shared__ char smem[];
    const uint32_t sb = smem_u32(smem);
    const int tid = threadIdx.x;
    const int wid = tid >> 5;
    const int lane = tid & 31;
    const int b = blockIdx.y;
    const int n0 = blockIdx.x * 64;

    const int wm = wid >> 2;
    const int wn = wid & 3;
    const int r = lane >> 2;
    const int c2 = (lane & 3) * 2;

    float* biasArr = (float*)(smem + SM_BIAS);
    for (int i = tid; i < 512; i += 256) {
        int which = i >> 7, c = i & 127;
        float v;
        if (which == 0) v = g_bfuse[c];
        else if (which == 1) v = g_be1[c];
        else if (which == 2) v = g_be2[c];
        else v = g_bp1[c];
        biasArr[i] = v;
    }
    float* bp2s = (float*)(smem + SM_BP2);
    if (tid < NCLS) bp2s[tid] = g_bp2[tid];
    float* wp2s = (float*)(smem + SM_WP2);
    for (int i = tid; i < NCLS * 128; i += 256) wp2s[i] = g_Wp2[i];

    float* Df = (float*)(smem + SM_D);
    float acc[2][4][4];
    float resid[2][4][4];

    // ---------------- L0: fuse
    cvt_global_to_op64(g_p1T + ((long)b * N_ + n0) * 128, 128, sb + SM_AOP);
    __syncthreads();
    zero_acc4(acc);
    mma_layer(sb + SM_AOP, g_Wfrag[0], acc, wm, wn, lane);
    __syncthreads();
    {
        float b0v[4], b1v[4];
#pragma unroll
        for (int nt = 0; nt < 4; ++nt) {
            int c = wn * 32 + nt * 8 + c2;
            b0v[nt] = biasArr[c];
            b1v[nt] = biasArr[c + 1];
        }
#pragma unroll
        for (int mt = 0; mt < 2; ++mt) {
#pragma unroll
            for (int half = 0; half < 2; ++half) {
                int row = wm * 32 + mt * 16 + half * 8 + r;
                long gb = ((long)b * N_ + n0 + row) * 3;
                int i0 = g_idx[gb], i1 = g_idx[gb + 1], i2 = g_idx[gb + 2];
                float w0 = g_w[gb], w1 = g_w[gb + 1], w2 = g_w[gb + 2];
                const float* z0 = g_ZY + ((long)b * S_ + i0) * 128;
                const float* z1 = g_ZY + ((long)b * S_ + i1) * 128;
                const float* z2 = g_ZY + ((long)b * S_ + i2) * 128;
#pragma unroll
                for (int nt = 0; nt < 4; ++nt) {
                    int c = wn * 32 + nt * 8 + c2;
                    float2 a0 = *(const float2*)(z0 + c);
                    float2 a1 = *(const float2*)(z1 + c);
                    float2 a2 = *(const float2*)(z2 + c);
                    float v0 = acc[mt][nt][half * 2 + 0] + b0v[nt]
                             + w0 * a0.x + w1 * a1.x + w2 * a2.x;
                    float v1 = acc[mt][nt][half * 2 + 1] + b1v[nt]
                             + w0 * a0.y + w1 * a1.y + w2 * a2.y;
                    v0 = fmaxf(v0, 0.f);
                    v1 = fmaxf(v1, 0.f);
                    acc[mt][nt][half * 2 + 0] = v0;
                    acc[mt][nt][half * 2 + 1] = v1;
                    resid[mt][nt][half * 2 + 0] = v0;
                    resid[mt][nt][half * 2 + 1] = v1;
                }
            }
        }
        epi_store(sb + SM_AOP, acc, wm, wn, lane);
    }
    __syncthreads();

    // ---------------- L1: ext1
    zero_acc4(acc);
    mma_layer(sb + SM_AOP, g_Wfrag[3], acc, wm, wn, lane);
    __syncthreads();
    {
#pragma unroll
        for (int mt = 0; mt < 2; ++mt)
#pragma unroll
            for (int nt = 0; nt < 4; ++nt) {
                int c = wn * 32 + nt * 8 + c2;
                acc[mt][nt][0] = fmaxf(acc[mt][nt][0] + biasArr[128 + c], 0.f);
                acc[mt][nt][1] = fmaxf(acc[mt][nt][1] + biasArr[128 + c + 1], 0.f);
                acc[mt][nt][2] = fmaxf(acc[mt][nt][2] + biasArr[128 + c], 0.f);
                acc[mt][nt][3] = fmaxf(acc[mt][nt][3] + biasArr[128 + c + 1], 0.f);
            }
        epi_store(sb + SM_AOP, acc, wm, wn, lane);
    }
    __syncthreads();

    // ---------------- L2: ext2 + residual
    zero_acc4(acc);
    mma_layer(sb + SM_AOP, g_Wfrag[4], acc, wm, wn, lane);
    __syncthreads();
    {
#pragma unroll
        for (int mt = 0; mt < 2; ++mt)
#pragma unroll
            for (int nt = 0; nt < 4; ++nt) {
                int c = wn * 32 + nt * 8 + c2;
                acc[mt][nt][0] = fmaxf(acc[mt][nt][0] + biasArr[256 + c] + resid[mt][nt][0], 0.f);
                acc[mt][nt][1] = fmaxf(acc[mt][nt][1] + biasArr[256 + c + 1] + resid[mt][nt][1], 0.f);
                acc[mt][nt][2] = fmaxf(acc[mt][nt][2] + biasArr[256 + c] + resid[mt][nt][2], 0.f);
                acc[mt][nt][3] = fmaxf(acc[mt][nt][3] + biasArr[256 + c + 1] + resid[mt][nt][3], 0.f);
            }
        epi_store(sb + SM_AOP, acc, wm, wn, lane);
        store_acc_to_D(Df, acc, wm, wn, lane);
    }
    __syncthreads();
    {
        float* o0 = out + OUT0_OFF + (long)b * 128 * N_ + n0;
        for (int c = wid; c < 128; c += 8) {
            float* dstc = o0 + (long)c * N_;
            for (int p = lane; p < 64; p += 32) dstc[p] = Df[p * DPITCH + c];
        }
    }

    // ---------------- L3: pred1
    zero_acc4(acc);
    mma_layer(sb + SM_AOP, g_Wfrag[5], acc, wm, wn, lane);
    __syncthreads();
    {
#pragma unroll
        for (int mt = 0; mt < 2; ++mt)
#pragma unroll
            for (int nt = 0; nt < 4; ++nt) {
                int c = wn * 32 + nt * 8 + c2;
                acc[mt][nt][0] = fmaxf(acc[mt][nt][0] + biasArr[384 + c], 0.f);
                acc[mt][nt][1] = fmaxf(acc[mt][nt][1] + biasArr[384 + c + 1], 0.f);
                acc[mt][nt][2] = fmaxf(acc[mt][nt][2] + biasArr[384 + c], 0.f);
                acc[mt][nt][3] = fmaxf(acc[mt][nt][3] + biasArr[384 + c + 1], 0.f);
            }
        store_acc_to_D(Df, acc, wm, wn, lane);
    }
    __syncthreads();

    {
        float* o1 = out + OUT1_OFF + ((long)b * N_ + n0) * 128;
        for (int idx = tid; idx < 2048; idx += 256) {
            int row = idx >> 5, c4 = idx & 31;
            float4 t = *(const float4*)(Df + row * DPITCH + c4 * 4);
            *(float4*)(o1 + row * 128 + c4 * 4) = t;
        }
    }
    for (int o = tid; o < 64 * NCLS; o += 256) {
        int pp = o / NCLS, j = o - pp * NCLS;
        const float* fr = Df + pp * DPITCH;
        const float* wr = wp2s + j * 128;
        float a = bp2s[j];
#pragma unroll 16
        for (int k = 0; k < 128; ++k) a = fmaf(fr[k], wr[k], a);
        out[OUT2_OFF + ((long)b * N_ + n0 + pp) * NCLS + j] = fmaxf(a, 0.f);
    }
}

// ---------------------------------------------------------------- launch
extern "C" void kernel_launch(void* const* d_in, const int* in_sizes, int n_in,
                              void* d_out, int out_size) {
    const float* xyz1      = (const float*)d_in[0];
    const float* xyz2      = (const float*)d_in[1];
    const float* points1   = (const float*)d_in[2];
    const float* points2   = (const float*)d_in[3];
    const float* last_pred = (const float*)d_in[4];
    const float* fuse_W = (const float*)d_in[5];
    const float* fuse_b = (const float*)d_in[6];
    const float* fuse_bn = (const float*)d_in[7];
    const float* e1_W = (const float*)d_in[8];
    const float* e1_b = (const float*)d_in[9];
    const float* e1_bn = (const float*)d_in[10];
    const float* e2_W = (const float*)d_in[11];
    const float* e2_b = (const float*)d_in[12];
    const float* e2_bn = (const float*)d_in[13];
    const float* p1_W = (const float*)d_in[14];
    const float* p1_b = (const float*)d_in[15];
    const float* p1_bn = (const float*)d_in[16];
    const float* p2_W = (const float*)d_in[17];
    const float* p2_b = (const float*)d_in[18];
    const float* p2_bn = (const float*)d_in[19];

    float* out = (float*)d_out;

    cudaFuncSetAttribute(front_kernel, cudaFuncAttributeMaxDynamicSharedMemorySize, FR_TOT);
    cudaFuncSetAttribute(zy_kernel, cudaFuncAttributeMaxDynamicSharedMemorySize, SM_TOT);
    cudaFuncSetAttribute(mega_kernel, cudaFuncAttributeMaxDynamicSharedMemorySize, SM_TOT);

    // [0] front: top3 (blocks 0-511, scheduled first) + prep + transposes
    front_kernel<<<FRONT_BLOCKS, 256, FR_TOT>>>(
        xyz1, xyz2, points1, points2,
        fuse_W, fuse_b, fuse_bn, e1_W, e1_b, e1_bn,
        e2_W, e2_b, e2_bn, p1_W, p1_b, p1_bn, p2_W, p2_b, p2_bn);
    // [1] ZY
    {
        dim3 grid(S_ / 64, B_);
        zy_kernel<<<grid, 256, SM_TOT>>>(last_pred);
    }
    // [2] mega
    {
        dim3 grid(N_ / 64, B_);
        mega_kernel<<<grid, 256, SM_TOT>>>(out);
    }
}